// round 4
// baseline (speedup 1.0000x reference)
#include <cuda_runtime.h>

#define NN 100000
#define EE 200000
#define KK 16
#define FF 32
#define EPS 1e-5f
#define RPB 64      // rows per block
#define RPW 8       // rows per warp
#define SMEM_BYTES (RPB*160*4 + 160*16*8)   // zsh 40960 + Wpk 20480 = 61440

// Scratch (static device globals — no allocation).
__device__ float g_pmpd[NN * FF];   // segment_sum(y, dst) -> [N, F]
__device__ float g_stats[128];      // [xsum32 | xssq32 | ysum32 | yssq32]

// ---------------------------------------------------------------------------
__global__ void k_zero() {
    int i = blockIdx.x * 256 + threadIdx.x;
    if (i < NN * FF) g_pmpd[i] = 0.f;
    if (i < 128) g_stats[i] = 0.f;
}

// segment_sum: warp per edge, lane = feature. 6.4M fp32 scatter-adds.
__global__ void k_scatter(const float* __restrict__ y, const int* __restrict__ dst) {
    int i = blockIdx.x * 256 + threadIdx.x;   // [0, EE*FF), exact
    int e = i >> 5, f = i & 31;
    int d = __ldg(&dst[e]);                    // broadcast within warp
    atomicAdd(&g_pmpd[d * FF + f], y[i]);
}

// ---------------------------------------------------------------------------
// Fused per-row kernel. Row z = [v, deg*v, sum_t, sum_tt, p] (160 floats),
// out = z @ Wbig + bias ; relu cols [16:32) ; BN stats accumulation.
// 256 threads = 8 warps = 64 rows/block.
//   Gather: warp per row, 8 rows sequentially, lane = feature (128B coalesced).
//   GEMM:   register-blocked — thread (g = lane>>4, o = lane&15) accumulates
//           4 rows x col-pair (o, o+16) with fma.rn.f32x2. W fetched once per
//           warp per j for 8 rows (4x less smem traffic than 2-row version).
// ---------------------------------------------------------------------------
__global__ __launch_bounds__(256) void k_main(
    const float* __restrict__ feat, const float* __restrict__ deg,
    const int* __restrict__ t, const int* __restrict__ tt,
    const float* __restrict__ psrc, const int* __restrict__ pidx,
    const float* __restrict__ w0, const float* __restrict__ w1,
    const float* __restrict__ w2, const float* __restrict__ w3,
    const float* __restrict__ w4,
    const float* __restrict__ b0, const float* __restrict__ b1,
    const float* __restrict__ b2, const float* __restrict__ b3,
    const float* __restrict__ b4,
    float* __restrict__ outp, int statoff, int nrows)
{
    extern __shared__ char smem[];
    float*  zsh = (float*)smem;                        // [RPB][160]
    float2* Wpk = (float2*)(smem + RPB * 160 * 4);     // [160][16]: {W[j][o], W[j][o+16]}
    __shared__ float biastot[32];
    __shared__ float s_sum[32], s_ssq[32];

    const float* pbase = psrc ? psrc : g_pmpd;
    float* stats = g_stats + statoff;

    int tid = threadIdx.x;
    // Stage packed weights.
    for (int i = tid; i < 160 * 16; i += 256) {
        int j = i >> 4, o = i & 15;
        const float* src = (j < 32) ? w0 : (j < 64) ? w1 : (j < 96) ? w2
                                   : (j < 128) ? w3 : w4;
        int jr = j & 31;
        Wpk[i] = make_float2(src[jr * 32 + o], src[jr * 32 + o + 16]);
    }
    if (tid < 32) {
        biastot[tid] = b0[tid] + b1[tid] + b2[tid] + b3[tid] + b4[tid];
        s_sum[tid] = 0.f; s_ssq[tid] = 0.f;
    }
    __syncthreads();

    int lane = tid & 31, warp = tid >> 5;
    int row0 = blockIdx.x * RPB;

    // ---- Gather phase: warp gathers its 8 rows ----
    for (int s = 0; s < RPW; s++) {
        int m = warp * RPW + s;
        int n = row0 + m;
        float* zr = zsh + m * 160;
        if (n < nrows) {            // warp-uniform branch
            float xv = feat[n * FF + lane];
            float dv = deg[n] * xv;
            int idxr = (lane < 16) ? t[n * KK + lane] : tt[n * KK + lane - 16];
            float a0 = 0.f, a1 = 0.f;
            #pragma unroll
            for (int k = 0; k < 16; k++) {
                int i0 = __shfl_sync(0xffffffffu, idxr, k);
                int i1 = __shfl_sync(0xffffffffu, idxr, k + 16);
                a0 += feat[i0 * FF + lane];
                a1 += feat[i1 * FF + lane];
            }
            float pv = pidx ? pbase[pidx[n] * FF + lane] : pbase[n * FF + lane];
            zr[lane]       = xv;
            zr[32 + lane]  = dv;
            zr[64 + lane]  = a0;
            zr[96 + lane]  = a1;
            zr[128 + lane] = pv;
        } else {
            zr[lane] = 0.f; zr[32 + lane] = 0.f; zr[64 + lane] = 0.f;
            zr[96 + lane] = 0.f; zr[128 + lane] = 0.f;
        }
    }
    __syncwarp();   // z produced & consumed within the same warp only

    // ---- GEMM phase: 4 rows per thread, packed f32x2 FMA ----
    int g = lane >> 4, o = lane & 15;
    int m0 = warp * RPW + g * 4;
    union U { unsigned long long u; float2 f; };
    U acc[4];
    #pragma unroll
    for (int r = 0; r < 4; r++) acc[r].f = make_float2(0.f, 0.f);

    const float* z0 = zsh + (m0 + 0) * 160;
    const float* z1 = zsh + (m0 + 1) * 160;
    const float* z2 = zsh + (m0 + 2) * 160;
    const float* z3 = zsh + (m0 + 3) * 160;

    #pragma unroll 2
    for (int j4 = 0; j4 < 160; j4 += 4) {
        float4 zv0 = *(const float4*)(z0 + j4);
        float4 zv1 = *(const float4*)(z1 + j4);
        float4 zv2 = *(const float4*)(z2 + j4);
        float4 zv3 = *(const float4*)(z3 + j4);
        U w[4];
        #pragma unroll
        for (int k = 0; k < 4; k++) w[k].f = Wpk[(j4 + k) * 16 + o];

        #define STEP(r, zc, k) { U a_;                                        \
            asm("mov.b64 %0, {%1,%1};" : "=l"(a_.u) : "f"(zc));               \
            asm("fma.rn.f32x2 %0, %1, %2, %0;"                                \
                : "+l"(acc[r].u) : "l"(a_.u), "l"(w[k].u)); }
        STEP(0, zv0.x, 0) STEP(0, zv0.y, 1) STEP(0, zv0.z, 2) STEP(0, zv0.w, 3)
        STEP(1, zv1.x, 0) STEP(1, zv1.y, 1) STEP(1, zv1.z, 2) STEP(1, zv1.w, 3)
        STEP(2, zv2.x, 0) STEP(2, zv2.y, 1) STEP(2, zv2.z, 2) STEP(2, zv2.w, 3)
        STEP(3, zv3.x, 0) STEP(3, zv3.y, 1) STEP(3, zv3.z, 2) STEP(3, zv3.w, 3)
        #undef STEP
    }

    float blo = biastot[o], bhi = biastot[o + 16];
    float slo = 0.f, sslo = 0.f, shi = 0.f, sshi = 0.f;
    #pragma unroll
    for (int r = 0; r < 4; r++) {
        int row = row0 + m0 + r;
        if (row < nrows) {
            float lo = acc[r].f.x + blo;
            float hi = fmaxf(acc[r].f.y + bhi, 0.f);   // relu on cols [16,32)
            outp[row * FF + o]      = lo;
            outp[row * FF + o + 16] = hi;
            slo += lo;  sslo += lo * lo;
            shi += hi;  sshi += hi * hi;
        }
    }
    // fold g0+g1 (same columns, different rows), then shared atomics
    slo  += __shfl_xor_sync(0xffffffffu, slo, 16);
    sslo += __shfl_xor_sync(0xffffffffu, sslo, 16);
    shi  += __shfl_xor_sync(0xffffffffu, shi, 16);
    sshi += __shfl_xor_sync(0xffffffffu, sshi, 16);
    if (lane < 16) {
        atomicAdd(&s_sum[o],      slo);
        atomicAdd(&s_ssq[o],      sslo);
        atomicAdd(&s_sum[o + 16], shi);
        atomicAdd(&s_ssq[o + 16], sshi);
    }
    __syncthreads();
    if (tid < 32) {
        atomicAdd(&stats[tid],      s_sum[tid]);
        atomicAdd(&stats[32 + tid], s_ssq[tid]);
    }
}

// ---------------------------------------------------------------------------
__global__ void k_norm(float* __restrict__ out,
                       const float* __restrict__ bnxw, const float* __restrict__ bnxb,
                       const float* __restrict__ bnyw, const float* __restrict__ bnyb)
{
    int i = blockIdx.x * 256 + threadIdx.x;
    if (i >= (NN + EE) * FF) return;
    int c = i & 31;
    bool isx = i < NN * FF;
    int base = isx ? 0 : 64;
    float cnt = isx ? (float)NN : (float)EE;
    float mean = g_stats[base + c] / cnt;
    float var  = g_stats[base + 32 + c] / cnt - mean * mean;
    float w = isx ? bnxw[c] : bnyw[c];
    float b = isx ? bnxb[c] : bnyb[c];
    out[i] = (out[i] - mean) * rsqrtf(var + EPS) * w + b;
}

// ---------------------------------------------------------------------------
extern "C" void kernel_launch(void* const* d_in, const int* in_sizes, int n_in,
                              void* d_out, int out_size)
{
    const float* x        = (const float*)d_in[0];
    const float* y        = (const float*)d_in[1];
    const float* deg_g    = (const float*)d_in[2];
    const float* deg_lg   = (const float*)d_in[3];
    const int*   t_g      = (const int*)d_in[4];
    const int*   tt_g     = (const int*)d_in[5];
    const int*   t_lg     = (const int*)d_in[6];
    const int*   tt_lg    = (const int*)d_in[7];
    const int*   dst      = (const int*)d_in[8];
    const int*   pm_pd    = (const int*)d_in[9];
    const float* theta_x_w   = (const float*)d_in[10];
    const float* theta_x_b   = (const float*)d_in[11];
    const float* theta_deg_w = (const float*)d_in[12];
    const float* theta_deg_b = (const float*)d_in[13];
    const float* theta_y_w   = (const float*)d_in[14];
    const float* theta_y_b   = (const float*)d_in[15];
    const float* gamma_y_w   = (const float*)d_in[16];
    const float* gamma_y_b   = (const float*)d_in[17];
    const float* gamma_deg_w = (const float*)d_in[18];
    const float* gamma_deg_b = (const float*)d_in[19];
    const float* gamma_x_w   = (const float*)d_in[20];
    const float* gamma_x_b   = (const float*)d_in[21];
    const float* theta_r_w   = (const float*)d_in[22];  // [2,32,32]
    const float* theta_r_b   = (const float*)d_in[23];  // [2,32]
    const float* gamma_r_w   = (const float*)d_in[24];
    const float* gamma_r_b   = (const float*)d_in[25];
    const float* bn_x_w      = (const float*)d_in[26];
    const float* bn_x_b      = (const float*)d_in[27];
    const float* bn_y_w      = (const float*)d_in[28];
    const float* bn_y_b      = (const float*)d_in[29];
    float* out = (float*)d_out;

    cudaFuncSetAttribute(k_main, cudaFuncAttributeMaxDynamicSharedMemorySize,
                         SMEM_BYTES);

    k_zero<<<(NN * FF + 255) / 256, 256>>>();
    k_scatter<<<EE * FF / 256, 256>>>(y, dst);

    // Node side: z = [x, deg*x, agg_t, agg_tt, pmpd_y]
    k_main<<<(NN + RPB - 1) / RPB, 256, SMEM_BYTES>>>(
        x, deg_g, t_g, tt_g, /*psrc=*/nullptr, /*pidx=*/nullptr,
        theta_x_w, theta_deg_w, theta_r_w, theta_r_w + 1024, theta_y_w,
        theta_x_b, theta_deg_b, theta_r_b, theta_r_b + 32, theta_y_b,
        out, /*statoff=*/0, NN);

    // Edge side: z = [y, deg*y, agg_t, agg_tt, x[pm_pd]]
    k_main<<<(EE + RPB - 1) / RPB, 256, SMEM_BYTES>>>(
        y, deg_lg, t_lg, tt_lg, /*psrc=*/x, /*pidx=*/pm_pd,
        gamma_y_w, gamma_deg_w, gamma_r_w, gamma_r_w + 1024, gamma_x_w,
        gamma_y_b, gamma_deg_b, gamma_r_b, gamma_r_b + 32, gamma_x_b,
        out + NN * FF, /*statoff=*/64, EE);

    k_norm<<<((NN + EE) * FF + 255) / 256, 256>>>(out, bn_x_w, bn_x_b, bn_y_w, bn_y_b);
}

// round 6
// speedup vs baseline: 1.9163x; 1.9163x over previous
#include <cuda_runtime.h>

#define NN 100000
#define EE 200000
#define KK 16
#define FF 32
#define EPS 1e-5f
#define RPB 32      // rows per block (NN, EE both divide exactly)
#define SMEM_BYTES (RPB*160*4 + 80*16*16)   // zsh 20480 + WT4 20480 = 40960

typedef unsigned long long ull;

// Scratch (static device globals — no allocation).
__device__ float g_pmpd[NN * FF];   // segment_sum(y, dst) -> [N, F]
__device__ float g_stats[128];      // [xsum32 | xssq32 | ysum32 | yssq32]

#define FMA2(acc, a, b) asm("fma.rn.f32x2 %0, %1, %2, %0;" : "+l"(acc) : "l"(a), "l"(b))

// ---------------------------------------------------------------------------
__global__ void k_zero() {
    int i = blockIdx.x * 256 + threadIdx.x;      // [0, NN*8)
    ((float4*)g_pmpd)[i] = make_float4(0.f, 0.f, 0.f, 0.f);
    if (i < 128) g_stats[i] = 0.f;
}

// segment_sum: warp per edge, lane = feature. 6.4M fp32 scatter-adds.
__global__ void k_scatter(const float* __restrict__ y, const int* __restrict__ dst) {
    int i = blockIdx.x * 256 + threadIdx.x;   // [0, EE*FF), exact
    int e = i >> 5, f = i & 31;
    int d = __ldg(&dst[e]);                    // broadcast within warp
    atomicAdd(&g_pmpd[d * FF + f], y[i]);
}

// ---------------------------------------------------------------------------
// Fused per-row kernel. Row z = [v, deg*v, sum_t, sum_tt, p] (160 floats),
// out = z @ Wbig + bias ; relu cols [16:32) ; BN stats accumulation.
// 256 threads = 8 warps = 32 rows/block (5 blocks/SM -> 40 warps, 62.5% occ).
//   Gather: warp per row-pair (2 interleaved rows for MLP), lane = feature.
//   GEMM:   thread (g=lane>>4, o=lane&15) does 2 rows x col-pair (o, o+16),
//           j-packed fma.rn.f32x2: z pairs come packed from LDS.128 (no movs),
//           W fetched as one LDS.128 per j2 giving both columns.
// ---------------------------------------------------------------------------
__global__ __launch_bounds__(256, 5) void k_main(
    const float* __restrict__ feat, const float* __restrict__ deg,
    const int* __restrict__ t, const int* __restrict__ tt,
    const float* __restrict__ psrc, const int* __restrict__ pidx,
    const float* __restrict__ w0, const float* __restrict__ w1,
    const float* __restrict__ w2, const float* __restrict__ w3,
    const float* __restrict__ w4,
    const float* __restrict__ b0, const float* __restrict__ b1,
    const float* __restrict__ b2, const float* __restrict__ b3,
    const float* __restrict__ b4,
    float* __restrict__ outp, int statoff)
{
    extern __shared__ char smem[];
    float* zsh = (float*)smem;                          // [RPB][160]
    float4* WT4s = (float4*)(smem + RPB * 160 * 4);     // [80][16] staging view
    const ulonglong2* WT4 = (const ulonglong2*)WT4s;    // read view
    __shared__ float biastot[32];
    __shared__ float s_sum[32], s_ssq[32];

    const float* pbase = psrc ? psrc : g_pmpd;
    float* stats = g_stats + statoff;

    int tid = threadIdx.x;
    // Stage packed weights: WT4[j2*16+o] = {W[2j2][o], W[2j2+1][o],
    //                                       W[2j2][o+16], W[2j2+1][o+16]}
    for (int i = tid; i < 80 * 16; i += 256) {
        int j2 = i >> 4, o = i & 15;
        int j = 2 * j2;
        const float* src = (j < 32) ? w0 : (j < 64) ? w1 : (j < 96) ? w2
                                   : (j < 128) ? w3 : w4;
        int jr = j & 31;          // j even -> j, j+1 share the same source block
        WT4s[i] = make_float4(src[jr * 32 + o],        src[(jr + 1) * 32 + o],
                              src[jr * 32 + o + 16],   src[(jr + 1) * 32 + o + 16]);
    }
    if (tid < 32) {
        biastot[tid] = b0[tid] + b1[tid] + b2[tid] + b3[tid] + b4[tid];
        s_sum[tid] = 0.f; s_ssq[tid] = 0.f;
    }
    __syncthreads();

    int lane = tid & 31, warp = tid >> 5;
    int row0 = blockIdx.x * RPB;
    int rbase = warp * 4;                 // 4 rows per warp

    // ---- Gather phase: 2 interleaved rows at a time (doubles load MLP) ----
    #pragma unroll
    for (int s = 0; s < 4; s += 2) {
        int m0 = rbase + s, m1 = m0 + 1;
        int n0 = row0 + m0, n1 = row0 + m1;
        float xv0 = feat[n0 * FF + lane];
        float xv1 = feat[n1 * FF + lane];
        float dv0 = deg[n0] * xv0;
        float dv1 = deg[n1] * xv1;
        int ir0 = (lane < 16) ? t[n0 * KK + lane] : tt[n0 * KK + lane - 16];
        int ir1 = (lane < 16) ? t[n1 * KK + lane] : tt[n1 * KK + lane - 16];
        float a00 = 0.f, a01 = 0.f, a10 = 0.f, a11 = 0.f;
        #pragma unroll
        for (int k = 0; k < 16; k++) {
            int i00 = __shfl_sync(0xffffffffu, ir0, k);
            int i01 = __shfl_sync(0xffffffffu, ir0, k + 16);
            int i10 = __shfl_sync(0xffffffffu, ir1, k);
            int i11 = __shfl_sync(0xffffffffu, ir1, k + 16);
            a00 += feat[i00 * FF + lane];
            a01 += feat[i01 * FF + lane];
            a10 += feat[i10 * FF + lane];
            a11 += feat[i11 * FF + lane];
        }
        float pv0 = pidx ? pbase[pidx[n0] * FF + lane] : pbase[n0 * FF + lane];
        float pv1 = pidx ? pbase[pidx[n1] * FF + lane] : pbase[n1 * FF + lane];
        float* zr0 = zsh + m0 * 160;
        float* zr1 = zsh + m1 * 160;
        zr0[lane] = xv0;       zr1[lane] = xv1;
        zr0[32 + lane] = dv0;  zr1[32 + lane] = dv1;
        zr0[64 + lane] = a00;  zr1[64 + lane] = a10;
        zr0[96 + lane] = a01;  zr1[96 + lane] = a11;
        zr0[128 + lane] = pv0; zr1[128 + lane] = pv1;
    }
    __syncwarp();   // z produced & consumed within the same warp only

    // ---- GEMM phase: thread = 2 rows x col-pair, j-packed f32x2 ----
    int g = lane >> 4, o = lane & 15;
    int mA = rbase + g * 2;               // rows mA, mA+1
    const float* zA = zsh + mA * 160;
    const float* zB = zsh + (mA + 1) * 160;

    ull accAlo = 0ull, accAhi = 0ull, accBlo = 0ull, accBhi = 0ull;
    #pragma unroll 4
    for (int j2 = 0; j2 < 80; j2 += 2) {
        ulonglong2 za = *(const ulonglong2*)(zA + j2 * 2);   // {z[j],z[j+1]},{z[j+2],z[j+3]}
        ulonglong2 zb = *(const ulonglong2*)(zB + j2 * 2);
        ulonglong2 wv0 = WT4[j2 * 16 + o];        // .x = lo-col pair, .y = hi-col pair
        ulonglong2 wv1 = WT4[(j2 + 1) * 16 + o];
        FMA2(accAlo, za.x, wv0.x);  FMA2(accAhi, za.x, wv0.y);
        FMA2(accAlo, za.y, wv1.x);  FMA2(accAhi, za.y, wv1.y);
        FMA2(accBlo, zb.x, wv0.x);  FMA2(accBhi, zb.x, wv0.y);
        FMA2(accBlo, zb.y, wv1.x);  FMA2(accBhi, zb.y, wv1.y);
    }

    union U { ull u; float2 f; } uAlo, uAhi, uBlo, uBhi;
    uAlo.u = accAlo; uAhi.u = accAhi; uBlo.u = accBlo; uBhi.u = accBhi;
    float blo = biastot[o], bhi = biastot[o + 16];

    float loA = uAlo.f.x + uAlo.f.y + blo;
    float hiA = fmaxf(uAhi.f.x + uAhi.f.y + bhi, 0.f);
    float loB = uBlo.f.x + uBlo.f.y + blo;
    float hiB = fmaxf(uBhi.f.x + uBhi.f.y + bhi, 0.f);

    int rA = row0 + mA;
    outp[rA * FF + o]            = loA;
    outp[rA * FF + o + 16]       = hiA;
    outp[(rA + 1) * FF + o]      = loB;
    outp[(rA + 1) * FF + o + 16] = hiB;

    // BN stats: fold 2 rows in-thread, fold g0/g1 via shuffle, shared atomics.
    float slo = loA + loB,        sslo = loA * loA + loB * loB;
    float shi = hiA + hiB,        sshi = hiA * hiA + hiB * hiB;
    slo  += __shfl_xor_sync(0xffffffffu, slo, 16);
    sslo += __shfl_xor_sync(0xffffffffu, sslo, 16);
    shi  += __shfl_xor_sync(0xffffffffu, shi, 16);
    sshi += __shfl_xor_sync(0xffffffffu, sshi, 16);
    if (lane < 16) {
        atomicAdd(&s_sum[o],      slo);
        atomicAdd(&s_ssq[o],      sslo);
        atomicAdd(&s_sum[o + 16], shi);
        atomicAdd(&s_ssq[o + 16], sshi);
    }
    __syncthreads();
    if (tid < 32) {
        atomicAdd(&stats[tid],      s_sum[tid]);
        atomicAdd(&stats[32 + tid], s_ssq[tid]);
    }
}

// ---------------------------------------------------------------------------
__global__ void k_norm(float* __restrict__ out,
                       const float* __restrict__ bnxw, const float* __restrict__ bnxb,
                       const float* __restrict__ bnyw, const float* __restrict__ bnyb)
{
    int i = blockIdx.x * 256 + threadIdx.x;       // [0, (NN+EE)*8), exact
    int c0 = (i & 7) * 4;
    bool isx = i < NN * 8;
    int base = isx ? 0 : 64;
    float cnt = isx ? (float)NN : (float)EE;
    const float* wv = isx ? bnxw : bnyw;
    const float* bv = isx ? bnxb : bnyb;
    float4 v = ((float4*)out)[i];
    float* vp = (float*)&v;
    #pragma unroll
    for (int k = 0; k < 4; k++) {
        int c = c0 + k;
        float mean = g_stats[base + c] / cnt;
        float var  = g_stats[base + 32 + c] / cnt - mean * mean;
        vp[k] = (vp[k] - mean) * rsqrtf(var + EPS) * wv[c] + bv[c];
    }
    ((float4*)out)[i] = v;
}

// ---------------------------------------------------------------------------
extern "C" void kernel_launch(void* const* d_in, const int* in_sizes, int n_in,
                              void* d_out, int out_size)
{
    const float* x        = (const float*)d_in[0];
    const float* y        = (const float*)d_in[1];
    const float* deg_g    = (const float*)d_in[2];
    const float* deg_lg   = (const float*)d_in[3];
    const int*   t_g      = (const int*)d_in[4];
    const int*   tt_g     = (const int*)d_in[5];
    const int*   t_lg     = (const int*)d_in[6];
    const int*   tt_lg    = (const int*)d_in[7];
    const int*   dst      = (const int*)d_in[8];
    const int*   pm_pd    = (const int*)d_in[9];
    const float* theta_x_w   = (const float*)d_in[10];
    const float* theta_x_b   = (const float*)d_in[11];
    const float* theta_deg_w = (const float*)d_in[12];
    const float* theta_deg_b = (const float*)d_in[13];
    const float* theta_y_w   = (const float*)d_in[14];
    const float* theta_y_b   = (const float*)d_in[15];
    const float* gamma_y_w   = (const float*)d_in[16];
    const float* gamma_y_b   = (const float*)d_in[17];
    const float* gamma_deg_w = (const float*)d_in[18];
    const float* gamma_deg_b = (const float*)d_in[19];
    const float* gamma_x_w   = (const float*)d_in[20];
    const float* gamma_x_b   = (const float*)d_in[21];
    const float* theta_r_w   = (const float*)d_in[22];  // [2,32,32]
    const float* theta_r_b   = (const float*)d_in[23];  // [2,32]
    const float* gamma_r_w   = (const float*)d_in[24];
    const float* gamma_r_b   = (const float*)d_in[25];
    const float* bn_x_w      = (const float*)d_in[26];
    const float* bn_x_b      = (const float*)d_in[27];
    const float* bn_y_w      = (const float*)d_in[28];
    const float* bn_y_b      = (const float*)d_in[29];
    float* out = (float*)d_out;

    cudaFuncSetAttribute(k_main, cudaFuncAttributeMaxDynamicSharedMemorySize,
                         SMEM_BYTES);

    k_zero<<<NN * 8 / 256, 256>>>();
    k_scatter<<<EE * FF / 256, 256>>>(y, dst);

    // Node side: z = [x, deg*x, agg_t, agg_tt, pmpd_y]
    k_main<<<NN / RPB, 256, SMEM_BYTES>>>(
        x, deg_g, t_g, tt_g, /*psrc=*/nullptr, /*pidx=*/nullptr,
        theta_x_w, theta_deg_w, theta_r_w, theta_r_w + 1024, theta_y_w,
        theta_x_b, theta_deg_b, theta_r_b, theta_r_b + 32, theta_y_b,
        out, /*statoff=*/0);

    // Edge side: z = [y, deg*y, agg_t, agg_tt, x[pm_pd]]
    k_main<<<EE / RPB, 256, SMEM_BYTES>>>(
        y, deg_lg, t_lg, tt_lg, /*psrc=*/x, /*pidx=*/pm_pd,
        gamma_y_w, gamma_deg_w, gamma_r_w, gamma_r_w + 1024, gamma_x_w,
        gamma_y_b, gamma_deg_b, gamma_r_b, gamma_r_b + 32, gamma_x_b,
        out + NN * FF, /*statoff=*/64);

    k_norm<<<(NN + EE) * 8 / 256, 256>>>(out, bn_x_w, bn_x_b, bn_y_w, bn_y_b);
}

// round 7
// speedup vs baseline: 1.9554x; 1.0204x over previous
#include <cuda_runtime.h>

#define NN 100000
#define EE 200000
#define KK 16
#define FF 32
#define EPS 1e-5f
#define RPB 32      // rows per block (NN, EE both divide exactly)
#define SMEM_BYTES (RPB*160*4 + 80*16*16)   // zsh 20480 + WT4 20480 = 40960

typedef unsigned long long ull;

// Scratch (static device globals — no allocation).
__device__ float g_pmpd[NN * FF];   // segment_sum(y, dst) -> [N, F]
__device__ float g_stats[128];      // [xsum32 | xssq32 | ysum32 | yssq32]

#define FMA2(acc, a, b) asm("fma.rn.f32x2 %0, %1, %2, %0;" : "+l"(acc) : "l"(a), "l"(b))
#define FADD2(acc, a)   asm("add.rn.f32x2 %0, %0, %1;"     : "+l"(acc) : "l"(a))

// ---------------------------------------------------------------------------
__global__ void k_zero() {
    int i = blockIdx.x * 256 + threadIdx.x;      // [0, NN*8)
    ((float4*)g_pmpd)[i] = make_float4(0.f, 0.f, 0.f, 0.f);
    if (i < 128) g_stats[i] = 0.f;
}

// segment_sum: warp per edge, lane = feature. 6.4M fp32 scatter-adds.
__global__ void k_scatter(const float* __restrict__ y, const int* __restrict__ dst) {
    int i = blockIdx.x * 256 + threadIdx.x;   // [0, EE*FF), exact
    int e = i >> 5, f = i & 31;
    int d = __ldg(&dst[e]);                    // broadcast within warp
    atomicAdd(&g_pmpd[d * FF + f], y[i]);
}

// ---------------------------------------------------------------------------
// Fused per-row kernel. Row z = [v, deg*v, sum_t, sum_tt, p] (160 floats),
// out = z @ Wbig + bias ; relu cols [16:32) ; BN stats accumulation.
// 256 threads = 8 warps = 32 rows/block (5 blocks/SM -> 62.5% occ).
//   Gather: LDG.64 two-neighbor-rows-per-instruction — lane half hb=lane>>4
//           picks neighbor 2q+hb, chunk l4=lane&15 picks float2 (2*l4,2*l4+1).
//           16 LDG.64 + 16 SHFL + 16 FADD2 per row (half of the R6 counts),
//           same 128 sectors/row. Fold with one shfl.xor(16) per accumulator.
//   GEMM:   unchanged from R6 — thread (g,o) = 2 rows x col-pair (o, o+16),
//           j-packed fma.rn.f32x2 from LDS.128 z and packed W table.
// ---------------------------------------------------------------------------
__global__ __launch_bounds__(256, 5) void k_main(
    const float* __restrict__ feat, const float* __restrict__ deg,
    const int* __restrict__ t, const int* __restrict__ tt,
    const float* __restrict__ psrc, const int* __restrict__ pidx,
    const float* __restrict__ w0, const float* __restrict__ w1,
    const float* __restrict__ w2, const float* __restrict__ w3,
    const float* __restrict__ w4,
    const float* __restrict__ b0, const float* __restrict__ b1,
    const float* __restrict__ b2, const float* __restrict__ b3,
    const float* __restrict__ b4,
    float* __restrict__ outp, int statoff)
{
    extern __shared__ char smem[];
    float* zsh = (float*)smem;                          // [RPB][160]
    float4* WT4s = (float4*)(smem + RPB * 160 * 4);     // [80][16] staging view
    const ulonglong2* WT4 = (const ulonglong2*)WT4s;    // read view
    __shared__ float biastot[32];
    __shared__ float s_sum[32], s_ssq[32];

    const float* pbase = psrc ? psrc : g_pmpd;
    float* stats = g_stats + statoff;

    int tid = threadIdx.x;
    // Stage packed weights: WT4[j2*16+o] = {W[2j2][o], W[2j2+1][o],
    //                                       W[2j2][o+16], W[2j2+1][o+16]}
    for (int i = tid; i < 80 * 16; i += 256) {
        int j2 = i >> 4, o = i & 15;
        int j = 2 * j2;
        const float* src = (j < 32) ? w0 : (j < 64) ? w1 : (j < 96) ? w2
                                   : (j < 128) ? w3 : w4;
        int jr = j & 31;          // j even -> j, j+1 share the same source block
        WT4s[i] = make_float4(src[jr * 32 + o],        src[(jr + 1) * 32 + o],
                              src[jr * 32 + o + 16],   src[(jr + 1) * 32 + o + 16]);
    }
    if (tid < 32) {
        biastot[tid] = b0[tid] + b1[tid] + b2[tid] + b3[tid] + b4[tid];
        s_sum[tid] = 0.f; s_ssq[tid] = 0.f;
    }
    __syncthreads();

    int lane = tid & 31, warp = tid >> 5;
    int row0 = blockIdx.x * RPB;
    int rbase = warp * 4;                 // 4 rows per warp
    int l4 = lane & 15;                   // float2 chunk within a 128B row
    int hb = lane >> 4;                   // which of the 2 rows this instr fetches
    const ull* fb = (const ull*)feat;     // feat as float2 (8B) elements

    // ---- Gather phase: 2 interleaved rows at a time ----
    #pragma unroll
    for (int s = 0; s < 4; s += 2) {
        int m0 = rbase + s, m1 = m0 + 1;
        int n0 = row0 + m0, n1 = row0 + m1;
        float xv0 = feat[n0 * FF + lane];
        float xv1 = feat[n1 * FF + lane];
        float dv0 = deg[n0] * xv0;
        float dv1 = deg[n1] * xv1;
        // lane<16 holds t indices, lane>=16 holds tt indices (16 each)
        int ir0 = (lane < 16) ? t[n0 * KK + lane] : tt[n0 * KK + lane - 16];
        int ir1 = (lane < 16) ? t[n1 * KK + lane] : tt[n1 * KK + lane - 16];

        ull a00 = 0ull, a01 = 0ull, a10 = 0ull, a11 = 0ull;  // {row,set} f32x2 accums
        #pragma unroll
        for (int q = 0; q < 8; q++) {
            int sl = 2 * q + hb;
            int i00 = __shfl_sync(0xffffffffu, ir0, sl);        // t,  row0
            int i01 = __shfl_sync(0xffffffffu, ir0, sl + 16);   // tt, row0
            int i10 = __shfl_sync(0xffffffffu, ir1, sl);        // t,  row1
            int i11 = __shfl_sync(0xffffffffu, ir1, sl + 16);   // tt, row1
            ull v00 = fb[i00 * 16 + l4];
            ull v01 = fb[i01 * 16 + l4];
            ull v10 = fb[i10 * 16 + l4];
            ull v11 = fb[i11 * 16 + l4];
            FADD2(a00, v00);
            FADD2(a01, v01);
            FADD2(a10, v10);
            FADD2(a11, v11);
        }
        // fold even/odd neighbor halves (lanes l and l^16 hold complements)
        ull f00 = __shfl_xor_sync(0xffffffffu, a00, 16); FADD2(a00, f00);
        ull f01 = __shfl_xor_sync(0xffffffffu, a01, 16); FADD2(a01, f01);
        ull f10 = __shfl_xor_sync(0xffffffffu, a10, 16); FADD2(a10, f10);
        ull f11 = __shfl_xor_sync(0xffffffffu, a11, 16); FADD2(a11, f11);

        float pv0 = pidx ? pbase[pidx[n0] * FF + lane] : pbase[n0 * FF + lane];
        float pv1 = pidx ? pbase[pidx[n1] * FF + lane] : pbase[n1 * FF + lane];
        float* zr0 = zsh + m0 * 160;
        float* zr1 = zsh + m1 * 160;
        zr0[lane] = xv0;       zr1[lane] = xv1;
        zr0[32 + lane] = dv0;  zr1[32 + lane] = dv1;
        // lanes 0-15 store the t-sum (z[64..96)), lanes 16-31 the tt-sum (z[96..128))
        union Uc { ull u; float2 f; } c0, c1;
        c0.u = hb ? a01 : a00;
        c1.u = hb ? a11 : a10;
        int zo = (hb ? 96 : 64) + 2 * l4;
        *(float2*)(zr0 + zo) = c0.f;
        *(float2*)(zr1 + zo) = c1.f;
        zr0[128 + lane] = pv0; zr1[128 + lane] = pv1;
    }
    __syncwarp();   // z produced & consumed within the same warp only

    // ---- GEMM phase: thread = 2 rows x col-pair, j-packed f32x2 ----
    int g = hb, o = l4;
    int mA = rbase + g * 2;               // rows mA, mA+1
    const float* zA = zsh + mA * 160;
    const float* zB = zsh + (mA + 1) * 160;

    ull accAlo = 0ull, accAhi = 0ull, accBlo = 0ull, accBhi = 0ull;
    #pragma unroll 4
    for (int j2 = 0; j2 < 80; j2 += 2) {
        ulonglong2 za = *(const ulonglong2*)(zA + j2 * 2);   // {z[j],z[j+1]},{z[j+2],z[j+3]}
        ulonglong2 zb = *(const ulonglong2*)(zB + j2 * 2);
        ulonglong2 wv0 = WT4[j2 * 16 + o];        // .x = lo-col pair, .y = hi-col pair
        ulonglong2 wv1 = WT4[(j2 + 1) * 16 + o];
        FMA2(accAlo, za.x, wv0.x);  FMA2(accAhi, za.x, wv0.y);
        FMA2(accAlo, za.y, wv1.x);  FMA2(accAhi, za.y, wv1.y);
        FMA2(accBlo, zb.x, wv0.x);  FMA2(accBhi, zb.x, wv0.y);
        FMA2(accBlo, zb.y, wv1.x);  FMA2(accBhi, zb.y, wv1.y);
    }

    union U { ull u; float2 f; } uAlo, uAhi, uBlo, uBhi;
    uAlo.u = accAlo; uAhi.u = accAhi; uBlo.u = accBlo; uBhi.u = accBhi;
    float blo = biastot[o], bhi = biastot[o + 16];

    float loA = uAlo.f.x + uAlo.f.y + blo;
    float hiA = fmaxf(uAhi.f.x + uAhi.f.y + bhi, 0.f);
    float loB = uBlo.f.x + uBlo.f.y + blo;
    float hiB = fmaxf(uBhi.f.x + uBhi.f.y + bhi, 0.f);

    int rA = row0 + mA;
    outp[rA * FF + o]            = loA;
    outp[rA * FF + o + 16]       = hiA;
    outp[(rA + 1) * FF + o]      = loB;
    outp[(rA + 1) * FF + o + 16] = hiB;

    // BN stats: fold 2 rows in-thread, fold g0/g1 via shuffle, shared atomics.
    float slo = loA + loB,        sslo = loA * loA + loB * loB;
    float shi = hiA + hiB,        sshi = hiA * hiA + hiB * hiB;
    slo  += __shfl_xor_sync(0xffffffffu, slo, 16);
    sslo += __shfl_xor_sync(0xffffffffu, sslo, 16);
    shi  += __shfl_xor_sync(0xffffffffu, shi, 16);
    sshi += __shfl_xor_sync(0xffffffffu, sshi, 16);
    if (lane < 16) {
        atomicAdd(&s_sum[o],      slo);
        atomicAdd(&s_ssq[o],      sslo);
        atomicAdd(&s_sum[o + 16], shi);
        atomicAdd(&s_ssq[o + 16], sshi);
    }
    __syncthreads();
    if (tid < 32) {
        atomicAdd(&stats[tid],      s_sum[tid]);
        atomicAdd(&stats[32 + tid], s_ssq[tid]);
    }
}

// ---------------------------------------------------------------------------
__global__ void k_norm(float* __restrict__ out,
                       const float* __restrict__ bnxw, const float* __restrict__ bnxb,
                       const float* __restrict__ bnyw, const float* __restrict__ bnyb)
{
    int i = blockIdx.x * 256 + threadIdx.x;       // [0, (NN+EE)*8), exact
    int c0 = (i & 7) * 4;
    bool isx = i < NN * 8;
    int base = isx ? 0 : 64;
    float cnt = isx ? (float)NN : (float)EE;
    const float* wv = isx ? bnxw : bnyw;
    const float* bv = isx ? bnxb : bnyb;
    float4 v = ((float4*)out)[i];
    float* vp = (float*)&v;
    #pragma unroll
    for (int k = 0; k < 4; k++) {
        int c = c0 + k;
        float mean = g_stats[base + c] / cnt;
        float var  = g_stats[base + 32 + c] / cnt - mean * mean;
        vp[k] = (vp[k] - mean) * rsqrtf(var + EPS) * wv[c] + bv[c];
    }
    ((float4*)out)[i] = v;
}

// ---------------------------------------------------------------------------
extern "C" void kernel_launch(void* const* d_in, const int* in_sizes, int n_in,
                              void* d_out, int out_size)
{
    const float* x        = (const float*)d_in[0];
    const float* y        = (const float*)d_in[1];
    const float* deg_g    = (const float*)d_in[2];
    const float* deg_lg   = (const float*)d_in[3];
    const int*   t_g      = (const int*)d_in[4];
    const int*   tt_g     = (const int*)d_in[5];
    const int*   t_lg     = (const int*)d_in[6];
    const int*   tt_lg    = (const int*)d_in[7];
    const int*   dst      = (const int*)d_in[8];
    const int*   pm_pd    = (const int*)d_in[9];
    const float* theta_x_w   = (const float*)d_in[10];
    const float* theta_x_b   = (const float*)d_in[11];
    const float* theta_deg_w = (const float*)d_in[12];
    const float* theta_deg_b = (const float*)d_in[13];
    const float* theta_y_w   = (const float*)d_in[14];
    const float* theta_y_b   = (const float*)d_in[15];
    const float* gamma_y_w   = (const float*)d_in[16];
    const float* gamma_y_b   = (const float*)d_in[17];
    const float* gamma_deg_w = (const float*)d_in[18];
    const float* gamma_deg_b = (const float*)d_in[19];
    const float* gamma_x_w   = (const float*)d_in[20];
    const float* gamma_x_b   = (const float*)d_in[21];
    const float* theta_r_w   = (const float*)d_in[22];  // [2,32,32]
    const float* theta_r_b   = (const float*)d_in[23];  // [2,32]
    const float* gamma_r_w   = (const float*)d_in[24];
    const float* gamma_r_b   = (const float*)d_in[25];
    const float* bn_x_w      = (const float*)d_in[26];
    const float* bn_x_b      = (const float*)d_in[27];
    const float* bn_y_w      = (const float*)d_in[28];
    const float* bn_y_b      = (const float*)d_in[29];
    float* out = (float*)d_out;

    cudaFuncSetAttribute(k_main, cudaFuncAttributeMaxDynamicSharedMemorySize,
                         SMEM_BYTES);

    k_zero<<<NN * 8 / 256, 256>>>();
    k_scatter<<<EE * FF / 256, 256>>>(y, dst);

    // Node side: z = [x, deg*x, agg_t, agg_tt, pmpd_y]
    k_main<<<NN / RPB, 256, SMEM_BYTES>>>(
        x, deg_g, t_g, tt_g, /*psrc=*/nullptr, /*pidx=*/nullptr,
        theta_x_w, theta_deg_w, theta_r_w, theta_r_w + 1024, theta_y_w,
        theta_x_b, theta_deg_b, theta_r_b, theta_r_b + 32, theta_y_b,
        out, /*statoff=*/0);

    // Edge side: z = [y, deg*y, agg_t, agg_tt, x[pm_pd]]
    k_main<<<EE / RPB, 256, SMEM_BYTES>>>(
        y, deg_lg, t_lg, tt_lg, /*psrc=*/x, /*pidx=*/pm_pd,
        gamma_y_w, gamma_deg_w, gamma_r_w, gamma_r_w + 1024, gamma_x_w,
        gamma_y_b, gamma_deg_b, gamma_r_b, gamma_r_b + 32, gamma_x_b,
        out + NN * FF, /*statoff=*/64);

    k_norm<<<(NN + EE) * 8 / 256, 256>>>(out, bn_x_w, bn_x_b, bn_y_w, bn_y_b);
}